// round 1
// baseline (speedup 1.0000x reference)
#include <cuda_runtime.h>
#include <cuda_bf16.h>
#include <math.h>

// Problem constants (MultiQueryAttention_56358560858478)
#define BB 2
#define TT 2048
#define DD 2048
#define HH 16
#define HD 128
#define MROWS (BB*TT)   // 4096

// ---------------- scratch (no allocation allowed) ----------------
__device__ float g_Q[MROWS * DD];    // (B,T,D) = (B,T,H,hd) layout
__device__ float g_K[MROWS * HD];    // (B,T,hd)
__device__ float g_V[MROWS * HD];    // (B,T,hd)
__device__ float g_AO[MROWS * DD];   // attention output (B,T,D)

// ---------------- generic tiled SGEMM with bias ----------------
// C[M,N] = A[M,K] @ B[K,N] + bias[N]; all row-major, dims divisible by tiles.
template<int BM, int BN, int BK, int TM, int TN>
__global__ __launch_bounds__((BM/TM)*(BN/TN))
void sgemm_bias(const float* __restrict__ A, const float* __restrict__ B,
                const float* __restrict__ bias, float* __restrict__ C,
                int M, int N, int K)
{
    __shared__ float As[BK][BM];
    __shared__ float Bs[BK][BN];
    constexpr int NT = (BM/TM)*(BN/TN);
    constexpr int TX = BN/TN;
    const int tid = threadIdx.x;
    const int tx = tid % TX;
    const int ty = tid / TX;
    const int m0 = blockIdx.y * BM;
    const int n0 = blockIdx.x * BN;

    float acc[TM][TN];
    #pragma unroll
    for (int i = 0; i < TM; i++)
        #pragma unroll
        for (int j = 0; j < TN; j++) acc[i][j] = 0.f;

    for (int kt = 0; kt < K; kt += BK) {
        // load A tile (BM x BK), transpose into As[k][m]
        #pragma unroll
        for (int i = tid; i < BM*BK/4; i += NT) {
            int r  = i / (BK/4);
            int c4 = (i % (BK/4)) * 4;
            float4 v = *(const float4*)&A[(m0 + r)*K + kt + c4];
            As[c4+0][r] = v.x; As[c4+1][r] = v.y;
            As[c4+2][r] = v.z; As[c4+3][r] = v.w;
        }
        // load B tile (BK x BN) straight
        #pragma unroll
        for (int i = tid; i < BK*BN/4; i += NT) {
            int r  = i / (BN/4);
            int c4 = (i % (BN/4)) * 4;
            *(float4*)&Bs[r][c4] = *(const float4*)&B[(kt + r)*N + n0 + c4];
        }
        __syncthreads();
        #pragma unroll
        for (int kk = 0; kk < BK; kk++) {
            float a[TM], b[TN];
            #pragma unroll
            for (int i = 0; i < TM; i++) a[i] = As[kk][ty*TM + i];
            #pragma unroll
            for (int j = 0; j < TN; j++) b[j] = Bs[kk][tx*TN + j];
            #pragma unroll
            for (int i = 0; i < TM; i++)
                #pragma unroll
                for (int j = 0; j < TN; j++)
                    acc[i][j] += a[i] * b[j];
        }
        __syncthreads();
    }

    #pragma unroll
    for (int i = 0; i < TM; i++) {
        int m = m0 + ty*TM + i;
        #pragma unroll
        for (int j = 0; j < TN; j += 4) {
            int n = n0 + tx*TN + j;
            float4 v;
            v.x = acc[i][j+0] + bias[n+0];
            v.y = acc[i][j+1] + bias[n+1];
            v.z = acc[i][j+2] + bias[n+2];
            v.w = acc[i][j+3] + bias[n+3];
            *(float4*)&C[m*N + n] = v;
        }
    }
}

// ---------------- flash attention (causal MQA, fp32) ----------------
// Q: (B,T,D) with head h at columns [h*HD, (h+1)*HD)
// K,V: (B,T,HD) shared across heads. Output AO: (B,T,D) same layout as Q.
#define BR 64
#define BC 64
#define QKV_STRIDE 129   // HD + 1 pad: conflict-free strided column access
#define PS_STRIDE  65    // BC + 1

#define FLASH_SMEM_FLOATS (BR*QKV_STRIDE /*Q*/ + BC*QKV_STRIDE /*K*/ + BC*QKV_STRIDE /*V*/ \
                           + BR*PS_STRIDE /*P*/ + 3*BR /*m,l,corr*/)
#define FLASH_SMEM_BYTES  (FLASH_SMEM_FLOATS * 4)

__global__ __launch_bounds__(256)
void flash_mqa(const float* __restrict__ Q, const float* __restrict__ Km,
               const float* __restrict__ Vm, float* __restrict__ O)
{
    extern __shared__ float sm[];
    float* Qs  = sm;                        // BR x QKV_STRIDE
    float* Ks  = Qs  + BR*QKV_STRIDE;       // BC x QKV_STRIDE
    float* Vs  = Ks  + BC*QKV_STRIDE;       // BC x QKV_STRIDE
    float* Ps  = Vs  + BC*QKV_STRIDE;       // BR x PS_STRIDE
    float* s_m = Ps  + BR*PS_STRIDE;        // BR
    float* s_l = s_m + BR;                  // BR
    float* s_c = s_l + BR;                  // BR

    const int qb = blockIdx.x;
    const int h  = blockIdx.y;
    const int b  = blockIdx.z;
    const int q0 = qb * BR;
    const int tid = threadIdx.x;
    const int tx = tid % 16;
    const int ty = tid / 16;

    const float scale = rsqrtf((float)HD);

    // load Q tile
    const float* Qbase = Q + (size_t)b*TT*DD + (size_t)h*HD;
    #pragma unroll
    for (int i = tid; i < BR*HD/4; i += 256) {
        int r = i / (HD/4);
        int c = (i % (HD/4)) * 4;
        float4 v = *(const float4*)&Qbase[(size_t)(q0 + r)*DD + c];
        Qs[r*QKV_STRIDE + c + 0] = v.x;
        Qs[r*QKV_STRIDE + c + 1] = v.y;
        Qs[r*QKV_STRIDE + c + 2] = v.z;
        Qs[r*QKV_STRIDE + c + 3] = v.w;
    }
    if (tid < BR) { s_m[tid] = -1e30f; s_l[tid] = 0.f; }

    float o[4][8];
    #pragma unroll
    for (int i = 0; i < 4; i++)
        #pragma unroll
        for (int j = 0; j < 8; j++) o[i][j] = 0.f;

    __syncthreads();

    const float* Kbase = Km + (size_t)b*TT*HD;
    const float* Vbase = Vm + (size_t)b*TT*HD;
    const int nkt = qb + 1;  // causal: key tiles 0..qb

    for (int kt = 0; kt < nkt; kt++) {
        const int k0 = kt * BC;
        // load K,V tiles
        #pragma unroll
        for (int i = tid; i < BC*HD/4; i += 256) {
            int r = i / (HD/4);
            int c = (i % (HD/4)) * 4;
            float4 kv = *(const float4*)&Kbase[(size_t)(k0 + r)*HD + c];
            Ks[r*QKV_STRIDE + c + 0] = kv.x;
            Ks[r*QKV_STRIDE + c + 1] = kv.y;
            Ks[r*QKV_STRIDE + c + 2] = kv.z;
            Ks[r*QKV_STRIDE + c + 3] = kv.w;
            float4 vv = *(const float4*)&Vbase[(size_t)(k0 + r)*HD + c];
            Vs[r*QKV_STRIDE + c + 0] = vv.x;
            Vs[r*QKV_STRIDE + c + 1] = vv.y;
            Vs[r*QKV_STRIDE + c + 2] = vv.z;
            Vs[r*QKV_STRIDE + c + 3] = vv.w;
        }
        __syncthreads();

        // S = Q @ K^T  (rows ty*4+i, cols tx + 16*j)
        float s[4][4];
        #pragma unroll
        for (int i = 0; i < 4; i++)
            #pragma unroll
            for (int j = 0; j < 4; j++) s[i][j] = 0.f;

        for (int k = 0; k < HD; k++) {
            float qv[4], kv[4];
            #pragma unroll
            for (int i = 0; i < 4; i++) qv[i] = Qs[(ty*4 + i)*QKV_STRIDE + k];
            #pragma unroll
            for (int j = 0; j < 4; j++) kv[j] = Ks[(tx + 16*j)*QKV_STRIDE + k];
            #pragma unroll
            for (int i = 0; i < 4; i++)
                #pragma unroll
                for (int j = 0; j < 4; j++)
                    s[i][j] += qv[i] * kv[j];
        }

        // scale + causal mask, store to Ps
        #pragma unroll
        for (int i = 0; i < 4; i++) {
            int r = ty*4 + i;
            #pragma unroll
            for (int j = 0; j < 4; j++) {
                int c = tx + 16*j;
                float val = s[i][j] * scale;
                if (k0 + c > q0 + r) val = -1e30f;
                Ps[r*PS_STRIDE + c] = val;
            }
        }
        __syncthreads();

        // online softmax per row (threads 0..63)
        if (tid < BR) {
            int r = tid;
            float mold = s_m[r];
            float mx = mold;
            #pragma unroll 8
            for (int j = 0; j < BC; j++) mx = fmaxf(mx, Ps[r*PS_STRIDE + j]);
            float corr = __expf(mold - mx);
            float sum = 0.f;
            #pragma unroll 8
            for (int j = 0; j < BC; j++) {
                float p = __expf(Ps[r*PS_STRIDE + j] - mx);
                Ps[r*PS_STRIDE + j] = p;
                sum += p;
            }
            s_l[r] = s_l[r]*corr + sum;
            s_m[r] = mx;
            s_c[r] = corr;
        }
        __syncthreads();

        // rescale O, then O += P @ V  (cols tx + 16*j)
        #pragma unroll
        for (int i = 0; i < 4; i++) {
            float corr = s_c[ty*4 + i];
            #pragma unroll
            for (int j = 0; j < 8; j++) o[i][j] *= corr;
        }
        for (int jk = 0; jk < BC; jk++) {
            float v[8];
            #pragma unroll
            for (int j = 0; j < 8; j++) v[j] = Vs[jk*QKV_STRIDE + tx + 16*j];
            #pragma unroll
            for (int i = 0; i < 4; i++) {
                float p = Ps[(ty*4 + i)*PS_STRIDE + jk];
                #pragma unroll
                for (int j = 0; j < 8; j++) o[i][j] += p * v[j];
            }
        }
        __syncthreads();  // protect Ks/Vs/Ps before next tile
    }

    // normalize and write out
    float* Ob = O + (size_t)b*TT*DD + (size_t)h*HD;
    #pragma unroll
    for (int i = 0; i < 4; i++) {
        int r = ty*4 + i;
        float inv = 1.f / s_l[r];
        #pragma unroll
        for (int j = 0; j < 8; j++) {
            Ob[(size_t)(q0 + r)*DD + tx + 16*j] = o[i][j] * inv;
        }
    }
}

// ---------------- launch ----------------
extern "C" void kernel_launch(void* const* d_in, const int* in_sizes, int n_in,
                              void* d_out, int out_size)
{
    const float* x  = (const float*)d_in[0];
    const float* Wq = (const float*)d_in[1];
    const float* bq = (const float*)d_in[2];
    const float* Wk = (const float*)d_in[3];
    const float* bk = (const float*)d_in[4];
    const float* Wv = (const float*)d_in[5];
    const float* bv = (const float*)d_in[6];
    const float* Wo = (const float*)d_in[7];
    const float* bo = (const float*)d_in[8];
    float* out = (float*)d_out;

    float *Qp, *Kp, *Vp, *AOp;
    cudaGetSymbolAddress((void**)&Qp,  g_Q);
    cudaGetSymbolAddress((void**)&Kp,  g_K);
    cudaGetSymbolAddress((void**)&Vp,  g_V);
    cudaGetSymbolAddress((void**)&AOp, g_AO);

    cudaFuncSetAttribute(flash_mqa, cudaFuncAttributeMaxDynamicSharedMemorySize,
                         FLASH_SMEM_BYTES);

    // Q = x @ Wq + bq   (4096 x 2048 x 2048)
    {
        dim3 grid(DD/128, MROWS/128);
        sgemm_bias<128,128,8,8,8><<<grid, 256>>>(x, Wq, bq, Qp, MROWS, DD, DD);
    }
    // K = x @ Wk + bk, V = x @ Wv + bv   (4096 x 128 x 2048)
    {
        dim3 grid(HD/64, MROWS/64);
        sgemm_bias<64,64,16,4,4><<<grid, 256>>>(x, Wk, bk, Kp, MROWS, HD, DD);
        sgemm_bias<64,64,16,4,4><<<grid, 256>>>(x, Wv, bv, Vp, MROWS, HD, DD);
    }
    // attention
    {
        dim3 grid(TT/BR, HH, BB);
        flash_mqa<<<grid, 256, FLASH_SMEM_BYTES>>>(Qp, Kp, Vp, AOp);
    }
    // out = AO @ Wo + bo   (4096 x 2048 x 2048)
    {
        dim3 grid(DD/128, MROWS/128);
        sgemm_bias<128,128,8,8,8><<<grid, 256>>>(AOp, Wo, bo, out, MROWS, DD, DD);
    }
}

// round 3
// speedup vs baseline: 3.3528x; 3.3528x over previous
#include <cuda_runtime.h>
#include <cuda_bf16.h>
#include <math.h>
#include <stdint.h>

// Problem constants (MultiQueryAttention_56358560858478)
#define BB 2
#define TT 2048
#define DD 2048
#define HH 16
#define HD 128
#define MROWS (BB*TT)   // 4096

// ---------------- scratch (no allocation allowed) ----------------
__device__ float g_Q[MROWS * DD];    // (B,T,D) = (B,T,H,hd) layout
__device__ float g_K[MROWS * HD];    // (B,T,hd)
__device__ float g_V[MROWS * HD];    // (B,T,hd)
__device__ float g_AO[MROWS * DD];   // attention output (B,T,D)

// ---------------- helpers ----------------
__device__ __forceinline__ float f2tf(float x) {
    uint32_t u;
    asm("cvt.rna.tf32.f32 %0, %1;" : "=r"(u) : "f"(x));
    return __uint_as_float(u);
}

__device__ __forceinline__ void mma_tf32(float* d, const uint32_t* a, const uint32_t* b) {
    asm volatile(
        "mma.sync.aligned.m16n8k8.row.col.f32.tf32.tf32.f32 "
        "{%0,%1,%2,%3}, {%4,%5,%6,%7}, {%8,%9}, {%0,%1,%2,%3};"
        : "+f"(d[0]), "+f"(d[1]), "+f"(d[2]), "+f"(d[3])
        : "r"(a[0]), "r"(a[1]), "r"(a[2]), "r"(a[3]), "r"(b[0]), "r"(b[1]));
}

// ---------------- tf32 tensor-core GEMM ----------------
// C[M,N] = A[M,K] @ B[K,N] + bias[N], row-major. M%128==0, N%128==0, K%32==0.
// 256 threads = 8 warps (4 row x 2 col), warp tile 32x64, block tile 128x128x32.
#define AS_ST 36    // A smem row stride (BK=32 + pad 4)
#define BS_ST 136   // B smem row stride (BN=128 + pad 8)
#define GEMM_SMEM ((2*128*AS_ST + 2*32*BS_ST) * 4)

__global__ __launch_bounds__(256)
void gemm_tf32(const float* __restrict__ A, const float* __restrict__ Bm,
               const float* __restrict__ bias, float* __restrict__ C,
               int M, int N, int K)
{
    extern __shared__ float sm[];
    float* As = sm;                    // [2][128][AS_ST]  (m, k)
    float* Bs = sm + 2*128*AS_ST;      // [2][32][BS_ST]   (k, n)

    const int tid  = threadIdx.x;
    const int lane = tid & 31;
    const int wid  = tid >> 5;
    const int grp  = lane >> 2;
    const int t4   = lane & 3;
    const int wm   = (wid & 3) * 32;
    const int wn   = (wid >> 2) * 64;
    const int m0   = blockIdx.y * 128;
    const int n0   = blockIdx.x * 128;

    // global load coords
    const int ar = tid >> 3;           // 0..31 (A rows, 4 passes of 32)
    const int ac = (tid & 7) * 4;      // 0..28
    const int br = tid >> 5;           // 0..7  (B rows, 4 passes of 8)
    const int bc = (tid & 31) * 4;     // 0..124

    float acc[2][8][4];
    #pragma unroll
    for (int mt = 0; mt < 2; mt++)
        #pragma unroll
        for (int nt = 0; nt < 8; nt++)
            #pragma unroll
            for (int e = 0; e < 4; e++) acc[mt][nt][e] = 0.f;

    // prologue: load tile 0 into stage 0
    {
        const float* Ap = A + (size_t)m0 * K;
        #pragma unroll
        for (int p = 0; p < 4; p++) {
            int r = ar + p*32;
            float4 v = *(const float4*)&Ap[(size_t)r*K + ac];
            float4 w = make_float4(f2tf(v.x), f2tf(v.y), f2tf(v.z), f2tf(v.w));
            *(float4*)&As[r*AS_ST + ac] = w;
        }
        const float* Bp = Bm + n0;
        #pragma unroll
        for (int p = 0; p < 4; p++) {
            int r = br + p*8;
            float4 v = *(const float4*)&Bp[(size_t)r*N + bc];
            float4 w = make_float4(f2tf(v.x), f2tf(v.y), f2tf(v.z), f2tf(v.w));
            *(float4*)&Bs[r*BS_ST + bc] = w;
        }
    }
    __syncthreads();

    for (int kt = 0; kt < K; kt += 32) {
        const int stage = (kt >> 5) & 1;
        const bool has_next = (kt + 32) < K;

        // issue next-tile global loads into registers
        float4 areg[4], breg[4];
        if (has_next) {
            const float* Ap = A + (size_t)m0 * K + (kt + 32);
            #pragma unroll
            for (int p = 0; p < 4; p++)
                areg[p] = *(const float4*)&Ap[(size_t)(ar + p*32)*K + ac];
            const float* Bp = Bm + (size_t)(kt + 32) * N + n0;
            #pragma unroll
            for (int p = 0; p < 4; p++)
                breg[p] = *(const float4*)&Bp[(size_t)(br + p*8)*N + bc];
        }

        // compute on current stage
        const float* as = &As[stage*128*AS_ST];
        const float* bs = &Bs[stage*32*BS_ST];
        #pragma unroll
        for (int ks = 0; ks < 4; ks++) {
            const int k0 = ks * 8;
            uint32_t af[2][4];
            #pragma unroll
            for (int mt = 0; mt < 2; mt++) {
                const float* ab = &as[(wm + mt*16 + grp)*AS_ST + k0 + t4];
                af[mt][0] = __float_as_uint(ab[0]);
                af[mt][1] = __float_as_uint(ab[8*AS_ST]);
                af[mt][2] = __float_as_uint(ab[4]);
                af[mt][3] = __float_as_uint(ab[8*AS_ST + 4]);
            }
            #pragma unroll
            for (int nt = 0; nt < 8; nt++) {
                uint32_t bf[2];
                const float* bb = &bs[(k0 + t4)*BS_ST + wn + nt*8 + grp];
                bf[0] = __float_as_uint(bb[0]);
                bf[1] = __float_as_uint(bb[4*BS_ST]);
                mma_tf32(acc[0][nt], af[0], bf);
                mma_tf32(acc[1][nt], af[1], bf);
            }
        }

        // store staged tile into other buffer (its readers finished last iter)
        if (has_next) {
            float* asn = &As[(stage^1)*128*AS_ST];
            float* bsn = &Bs[(stage^1)*32*BS_ST];
            #pragma unroll
            for (int p = 0; p < 4; p++) {
                float4 v = areg[p];
                float4 w = make_float4(f2tf(v.x), f2tf(v.y), f2tf(v.z), f2tf(v.w));
                *(float4*)&asn[(ar + p*32)*AS_ST + ac] = w;
            }
            #pragma unroll
            for (int p = 0; p < 4; p++) {
                float4 v = breg[p];
                float4 w = make_float4(f2tf(v.x), f2tf(v.y), f2tf(v.z), f2tf(v.w));
                *(float4*)&bsn[(br + p*8)*BS_ST + bc] = w;
            }
        }
        __syncthreads();
    }

    // epilogue
    #pragma unroll
    for (int mt = 0; mt < 2; mt++) {
        const int r = m0 + wm + mt*16 + grp;
        #pragma unroll
        for (int nt = 0; nt < 8; nt++) {
            const int c = n0 + wn + nt*8 + 2*t4;
            const float bz0 = bias[c], bz1 = bias[c+1];
            float2 v0 = make_float2(acc[mt][nt][0] + bz0, acc[mt][nt][1] + bz1);
            *(float2*)&C[(size_t)r*N + c] = v0;
            float2 v1 = make_float2(acc[mt][nt][2] + bz0, acc[mt][nt][3] + bz1);
            *(float2*)&C[(size_t)(r+8)*N + c] = v1;
        }
    }
}

// ---------------- flash attention, tf32 tensor cores ----------------
// 256 threads = 8 warps; each warp owns 16 query rows. BR=128, BC=64.
// Q kept in registers as A-fragments (pre-scaled). K/V staged in smem (tf32).
// P goes through per-warp smem region to convert C-layout -> A-layout.
#define FB_R 128
#define FB_C 64
#define KS_ST 132   // HD + 4
#define VS_ST 136   // HD + 8
#define PS_ST 68    // BC + 4
#define FLASH_SMEM ((FB_C*KS_ST + FB_C*VS_ST + FB_R*PS_ST) * 4)

__global__ __launch_bounds__(256)
void flash_tf32(const float* __restrict__ Q, const float* __restrict__ Kg,
                const float* __restrict__ Vg, float* __restrict__ O)
{
    extern __shared__ float sm[];
    float* Ks = sm;                       // [64][KS_ST]
    float* Vs = Ks + FB_C*KS_ST;          // [64][VS_ST]
    float* Ps = Vs + FB_C*VS_ST;          // [8][16][PS_ST]

    const int tid  = threadIdx.x;
    const int lane = tid & 31;
    const int wid  = tid >> 5;
    const int grp  = lane >> 2;
    const int t4   = lane & 3;

    const int qb = gridDim.x - 1 - blockIdx.x;   // longest blocks first
    const int h  = blockIdx.y;
    const int b  = blockIdx.z;
    const int q0 = qb * FB_R;
    const int qr = q0 + wid*16 + grp;            // low row; high row = qr + 8

    const float scale = 0.08838834764831845f;    // 1/sqrt(128)

    // ---- load Q fragments (scaled, tf32) into registers ----
    const float* Qb = Q + (size_t)b*TT*DD + (size_t)h*HD;
    uint32_t qf[16][4];
    #pragma unroll
    for (int ks = 0; ks < 16; ks++) {
        const float* p0 = &Qb[(size_t)qr*DD + ks*8 + t4];
        qf[ks][0] = __float_as_uint(f2tf(p0[0]        * scale));
        qf[ks][1] = __float_as_uint(f2tf(p0[8*DD]     * scale));
        qf[ks][2] = __float_as_uint(f2tf(p0[4]        * scale));
        qf[ks][3] = __float_as_uint(f2tf(p0[8*DD + 4] * scale));
    }

    float of[16][4];
    #pragma unroll
    for (int nt = 0; nt < 16; nt++)
        #pragma unroll
        for (int e = 0; e < 4; e++) of[nt][e] = 0.f;

    float m_lo = -1e30f, m_hi = -1e30f, l_lo = 0.f, l_hi = 0.f;

    const float* Kb = Kg + (size_t)b*TT*HD;
    const float* Vb = Vg + (size_t)b*TT*HD;
    float* Pw = Ps + wid*16*PS_ST;
    const int nkt = 2*(qb + 1);

    const int lr = tid >> 5;           // K/V load row 0..7 (8 passes)
    const int lc = (tid & 31) * 4;     // col 0..124

    for (int kt = 0; kt < nkt; kt++) {
        const int k0 = kt * FB_C;
        __syncthreads();   // prior iteration's Ks/Vs reads complete
        #pragma unroll
        for (int p = 0; p < 8; p++) {
            int rr = lr + p*8;
            float4 kv = *(const float4*)&Kb[(size_t)(k0 + rr)*HD + lc];
            float4 wk = make_float4(f2tf(kv.x), f2tf(kv.y), f2tf(kv.z), f2tf(kv.w));
            *(float4*)&Ks[rr*KS_ST + lc] = wk;
            float4 vv = *(const float4*)&Vb[(size_t)(k0 + rr)*HD + lc];
            float4 wv = make_float4(f2tf(vv.x), f2tf(vv.y), f2tf(vv.z), f2tf(vv.w));
            *(float4*)&Vs[rr*VS_ST + lc] = wv;
        }
        __syncthreads();

        // ---- S = Q @ K^T (scaled) ----
        float sacc[8][4];
        #pragma unroll
        for (int nt = 0; nt < 8; nt++)
            #pragma unroll
            for (int e = 0; e < 4; e++) sacc[nt][e] = 0.f;

        #pragma unroll
        for (int ks = 0; ks < 16; ks++) {
            #pragma unroll
            for (int nt = 0; nt < 8; nt++) {
                uint32_t bf[2];
                const float* kb = &Ks[(nt*8 + grp)*KS_ST + ks*8 + t4];
                bf[0] = __float_as_uint(kb[0]);
                bf[1] = __float_as_uint(kb[4]);
                mma_tf32(sacc[nt], qf[ks], bf);
            }
        }

        // ---- causal mask (only last two tiles overlap the diagonal) ----
        if (kt >= nkt - 2) {
            #pragma unroll
            for (int nt = 0; nt < 8; nt++) {
                int kc = k0 + nt*8 + 2*t4;
                if (kc     > qr)     sacc[nt][0] = -1e30f;
                if (kc + 1 > qr)     sacc[nt][1] = -1e30f;
                if (kc     > qr + 8) sacc[nt][2] = -1e30f;
                if (kc + 1 > qr + 8) sacc[nt][3] = -1e30f;
            }
        }

        // ---- online softmax (rows live in 4-lane groups) ----
        float mx_lo = -1e30f, mx_hi = -1e30f;
        #pragma unroll
        for (int nt = 0; nt < 8; nt++) {
            mx_lo = fmaxf(mx_lo, fmaxf(sacc[nt][0], sacc[nt][1]));
            mx_hi = fmaxf(mx_hi, fmaxf(sacc[nt][2], sacc[nt][3]));
        }
        mx_lo = fmaxf(mx_lo, __shfl_xor_sync(0xffffffffu, mx_lo, 1));
        mx_lo = fmaxf(mx_lo, __shfl_xor_sync(0xffffffffu, mx_lo, 2));
        mx_hi = fmaxf(mx_hi, __shfl_xor_sync(0xffffffffu, mx_hi, 1));
        mx_hi = fmaxf(mx_hi, __shfl_xor_sync(0xffffffffu, mx_hi, 2));

        const float mn_lo = fmaxf(m_lo, mx_lo);
        const float mn_hi = fmaxf(m_hi, mx_hi);
        const float corr_lo = __expf(m_lo - mn_lo);
        const float corr_hi = __expf(m_hi - mn_hi);

        float sum_lo = 0.f, sum_hi = 0.f;
        #pragma unroll
        for (int nt = 0; nt < 8; nt++) {
            sacc[nt][0] = __expf(sacc[nt][0] - mn_lo);
            sacc[nt][1] = __expf(sacc[nt][1] - mn_lo);
            sacc[nt][2] = __expf(sacc[nt][2] - mn_hi);
            sacc[nt][3] = __expf(sacc[nt][3] - mn_hi);
            sum_lo += sacc[nt][0] + sacc[nt][1];
            sum_hi += sacc[nt][2] + sacc[nt][3];
        }
        sum_lo += __shfl_xor_sync(0xffffffffu, sum_lo, 1);
        sum_lo += __shfl_xor_sync(0xffffffffu, sum_lo, 2);
        sum_hi += __shfl_xor_sync(0xffffffffu, sum_hi, 1);
        sum_hi += __shfl_xor_sync(0xffffffffu, sum_hi, 2);

        l_lo = l_lo * corr_lo + sum_lo;  m_lo = mn_lo;
        l_hi = l_hi * corr_hi + sum_hi;  m_hi = mn_hi;

        // rescale O accumulators
        #pragma unroll
        for (int nt = 0; nt < 16; nt++) {
            of[nt][0] *= corr_lo;  of[nt][1] *= corr_lo;
            of[nt][2] *= corr_hi;  of[nt][3] *= corr_hi;
        }

        // ---- P through per-warp smem (C-layout -> A-layout), tf32 ----
        #pragma unroll
        for (int nt = 0; nt < 8; nt++) {
            float2 p01 = make_float2(f2tf(sacc[nt][0]), f2tf(sacc[nt][1]));
            *(float2*)&Pw[grp*PS_ST + nt*8 + 2*t4] = p01;
            float2 p23 = make_float2(f2tf(sacc[nt][2]), f2tf(sacc[nt][3]));
            *(float2*)&Pw[(grp + 8)*PS_ST + nt*8 + 2*t4] = p23;
        }
        __syncwarp();

        // ---- O += P @ V ----
        #pragma unroll
        for (int ks = 0; ks < 8; ks++) {
            uint32_t pf[4];
            const float* pb = &Pw[grp*PS_ST + ks*8 + t4];
            pf[0] = __float_as_uint(pb[0]);
            pf[1] = __float_as_uint(pb[8*PS_ST]);
            pf[2] = __float_as_uint(pb[4]);
            pf[3] = __float_as_uint(pb[8*PS_ST + 4]);
            #pragma unroll
            for (int nt = 0; nt < 16; nt++) {
                uint32_t bf[2];
                const float* vb = &Vs[(ks*8 + t4)*VS_ST + nt*8 + grp];
                bf[0] = __float_as_uint(vb[0]);
                bf[1] = __float_as_uint(vb[4*VS_ST]);
                mma_tf32(of[nt], pf, bf);
            }
        }
        // top-of-loop __syncthreads orders Pw/Ks/Vs reuse across iterations
    }

    // ---- normalize and write ----
    const float inv_lo = 1.f / l_lo;
    const float inv_hi = 1.f / l_hi;
    float* Ob = O + (size_t)b*TT*DD + (size_t)h*HD;
    #pragma unroll
    for (int nt = 0; nt < 16; nt++) {
        const int c = nt*8 + 2*t4;
        float2 v0 = make_float2(of[nt][0]*inv_lo, of[nt][1]*inv_lo);
        *(float2*)&Ob[(size_t)qr*DD + c] = v0;
        float2 v1 = make_float2(of[nt][2]*inv_hi, of[nt][3]*inv_hi);
        *(float2*)&Ob[(size_t)(qr + 8)*DD + c] = v1;
    }
}

// ---------------- launch ----------------
extern "C" void kernel_launch(void* const* d_in, const int* in_sizes, int n_in,
                              void* d_out, int out_size)
{
    const float* x  = (const float*)d_in[0];
    const float* Wq = (const float*)d_in[1];
    const float* bq = (const float*)d_in[2];
    const float* Wk = (const float*)d_in[3];
    const float* bk = (const float*)d_in[4];
    const float* Wv = (const float*)d_in[5];
    const float* bv = (const float*)d_in[6];
    const float* Wo = (const float*)d_in[7];
    const float* bo = (const float*)d_in[8];
    float* out = (float*)d_out;

    float *Qp, *Kp, *Vp, *AOp;
    cudaGetSymbolAddress((void**)&Qp,  g_Q);
    cudaGetSymbolAddress((void**)&Kp,  g_K);
    cudaGetSymbolAddress((void**)&Vp,  g_V);
    cudaGetSymbolAddress((void**)&AOp, g_AO);

    // unconditional every call: no static guards allowed in kernel_launch
    cudaFuncSetAttribute(gemm_tf32, cudaFuncAttributeMaxDynamicSharedMemorySize, GEMM_SMEM);
    cudaFuncSetAttribute(flash_tf32, cudaFuncAttributeMaxDynamicSharedMemorySize, FLASH_SMEM);

    // Q = x @ Wq + bq   (4096 x 2048 x 2048)
    gemm_tf32<<<dim3(DD/128, MROWS/128), 256, GEMM_SMEM>>>(x, Wq, bq, Qp, MROWS, DD, DD);
    // K = x @ Wk + bk, V = x @ Wv + bv   (4096 x 128 x 2048)
    gemm_tf32<<<dim3(HD/128, MROWS/128), 256, GEMM_SMEM>>>(x, Wk, bk, Kp, MROWS, HD, DD);
    gemm_tf32<<<dim3(HD/128, MROWS/128), 256, GEMM_SMEM>>>(x, Wv, bv, Vp, MROWS, HD, DD);
    // attention
    flash_tf32<<<dim3(TT/FB_R, HH, BB), 256, FLASH_SMEM>>>(Qp, Kp, Vp, AOp);
    // out = AO @ Wo + bo  (4096 x 2048 x 2048)
    gemm_tf32<<<dim3(DD/128, MROWS/128), 256, GEMM_SMEM>>>(AOp, Wo, bo, out, MROWS, DD, DD);
}

// round 5
// speedup vs baseline: 4.0648x; 1.2124x over previous
#include <cuda_runtime.h>
#include <cuda_bf16.h>
#include <math.h>
#include <stdint.h>

// Problem constants (MultiQueryAttention_56358560858478)
#define BB 2
#define TT 2048
#define DD 2048
#define HH 16
#define HD 128
#define MROWS (BB*TT)   // 4096

// ---------------- scratch (no allocation allowed) ----------------
__device__ float  g_Q [MROWS * DD];     // Q projection (B,T,D)
__device__ float  g_K [MROWS * HD];
__device__ float  g_V [MROWS * HD];
__device__ float  g_AO[MROWS * DD];     // attention output, row-major
__device__ float4 g_Xp [MROWS * DD / 4];  // x packed (A-fragment order, tf32)
__device__ float4 g_AOp[MROWS * DD / 4];  // AO packed
__device__ float4 g_WqP[DD * DD / 4];     // weights packed (B-fragment order, tf32)
__device__ float4 g_WkP[DD * HD / 4];
__device__ float4 g_WvP[DD * HD / 4];
__device__ float4 g_WoP[DD * DD / 4];

// ---------------- helpers ----------------
__device__ __forceinline__ float f2tf(float x) {
    uint32_t u;
    asm("cvt.rna.tf32.f32 %0, %1;" : "=r"(u) : "f"(x));
    return __uint_as_float(u);
}

__device__ __forceinline__ uint32_t s2u(const void* p) {
    uint32_t a;
    asm("{ .reg .u64 t; cvta.to.shared.u64 t, %1; cvt.u32.u64 %0, t; }" : "=r"(a) : "l"(p));
    return a;
}

__device__ __forceinline__ void mma_tf32(float* d, const uint32_t* a, const uint32_t* b) {
    asm volatile(
        "mma.sync.aligned.m16n8k8.row.col.f32.tf32.tf32.f32 "
        "{%0,%1,%2,%3}, {%4,%5,%6,%7}, {%8,%9}, {%0,%1,%2,%3};"
        : "+f"(d[0]), "+f"(d[1]), "+f"(d[2]), "+f"(d[3])
        : "r"(a[0]), "r"(a[1]), "r"(a[2]), "r"(a[3]), "r"(b[0]), "r"(b[1]));
}

// ================= operand packing =================
// A-fragment order (per 128xM-tile x 32-K-tile, 4096 floats):
//   offset = ks*1024 + mt*128 + lane*4 + reg
//   m = mb*128 + mt*16 + (reg&1)*8 + (lane>>2);  k = kc*32 + ks*8 + (reg>>1)*4 + (lane&3)
__global__ void pack_A(const float* __restrict__ src, float4* __restrict__ dst, int M, int K) {
    const int o = blockIdx.x * 256 + threadIdx.x;   // one output float4
    const int lane = o & 31;
    const int mt   = (o >> 5) & 7;
    const int ks   = (o >> 8) & 3;
    const int tile = o >> 10;
    const int KT = K >> 5;
    const int kc = tile % KT;
    const int mb = tile / KT;
    const int m = mb*128 + mt*16 + (lane >> 2);
    const int k = kc*32 + ks*8 + (lane & 3);
    const float* s = src + (size_t)m * K + k;
    float4 v;
    v.x = f2tf(s[0]);
    v.y = f2tf(s[(size_t)8 * K]);
    v.z = f2tf(s[4]);
    v.w = f2tf(s[(size_t)8 * K + 4]);
    dst[o] = v;
}

// B-fragment order (per 128xN-tile x 32-K-tile, 4096 floats as 2048 float2):
//   offset(float2) = ks*512 + ng*32 + lane;   {b0,b1} = W[k][n], W[k+4][n]
//   n = nb*128 + ng*8 + (lane>>2);  k = kc*32 + ks*8 + (lane&3)
__global__ void pack_B(const float* __restrict__ src, float2* __restrict__ dst, int N, int K) {
    const int o = blockIdx.x * 256 + threadIdx.x;   // one output float2
    const int lane = o & 31;
    const int ng   = (o >> 5) & 15;
    const int ks   = (o >> 9) & 3;
    const int tile = o >> 11;
    const int KT = K >> 5;
    const int kc = tile % KT;
    const int nb = tile / KT;
    const int n = nb*128 + ng*8 + (lane >> 2);
    const int k = kc*32 + ks*8 + (lane & 3);
    const float* s = src + (size_t)k * N + n;
    dst[o] = make_float2(f2tf(s[0]), f2tf(s[(size_t)4 * N]));
}

// ================= mma.sync GEMM, fragment-packed operands =================
// C[M,N] = A @ B + bias. Tile 128x128x32, 256 threads (8 warps, warp 32x64),
// 3-stage cp.async pipeline. Ap/Bp are packed as above.
#define G_STAGE_F 8192                 // floats per stage (A 4096 + B 4096)
#define G_SMEM (3 * G_STAGE_F * 4)     // 96 KB

__global__ __launch_bounds__(256)
void gemm_mma(const float4* __restrict__ Ap, const float4* __restrict__ Bp,
              const float* __restrict__ bias, float* __restrict__ C,
              int M, int N, int K)
{
    extern __shared__ float sm[];
    const int tid = threadIdx.x, lane = tid & 31, wid = tid >> 5;
    const int grp = lane >> 2, t4 = lane & 3;
    const int mb = blockIdx.y, nb = blockIdx.x;
    const int KT = K >> 5, NC = KT;

    const float4* At = Ap + (size_t)mb * KT * 1024;
    const float4* Bt = Bp + (size_t)nb * KT * 1024;

    float acc[2][8][4];
    #pragma unroll
    for (int i = 0; i < 2; i++)
        #pragma unroll
        for (int j = 0; j < 8; j++)
            #pragma unroll
            for (int e = 0; e < 4; e++) acc[i][j][e] = 0.f;

    auto fill = [&](int ch) {
        const int s = ch % 3;
        const uint32_t da = s2u(sm + s * G_STAGE_F);
        const float4* a = At + (size_t)ch * 1024;
        const float4* b = Bt + (size_t)ch * 1024;
        #pragma unroll
        for (int i = tid; i < 1024; i += 256)
            asm volatile("cp.async.cg.shared.global [%0], [%1], 16;"
                         :: "r"(da + i*16), "l"(a + i));
        const uint32_t db = da + 4096*4;
        #pragma unroll
        for (int i = tid; i < 1024; i += 256)
            asm volatile("cp.async.cg.shared.global [%0], [%1], 16;"
                         :: "r"(db + i*16), "l"(b + i));
        asm volatile("cp.async.commit_group;" ::: "memory");
    };

    fill(0);
    if (NC > 1) fill(1);

    const int mtb = (wid & 3) * 2;      // warp's first 16-row tile (0..7)
    const int ngb = (wid >> 2) * 8;     // warp's first n8 group (0 or 8)

    for (int i = 0; i < NC; i++) {
        if (i + 2 < NC) asm volatile("cp.async.wait_group 1;" ::: "memory");
        else            asm volatile("cp.async.wait_group 0;" ::: "memory");
        __syncthreads();
        if (i + 2 < NC) fill(i + 2);

        const float* sa = sm + (i % 3) * G_STAGE_F;
        const float* sb = sa + 4096;
        #pragma unroll
        for (int ks = 0; ks < 4; ks++) {
            float4 a0 = *(const float4*)&sa[ks*1024 + (mtb + 0)*128 + lane*4];
            float4 a1 = *(const float4*)&sa[ks*1024 + (mtb + 1)*128 + lane*4];
            #pragma unroll
            for (int nt = 0; nt < 8; nt++) {
                float2 b = *(const float2*)&sb[ks*1024 + (ngb + nt)*64 + lane*2];
                mma_tf32(acc[0][nt], (const uint32_t*)&a0, (const uint32_t*)&b);
                mma_tf32(acc[1][nt], (const uint32_t*)&a1, (const uint32_t*)&b);
            }
        }
        __syncthreads();   // all reads of stage i%3 done before it is refilled
    }

    // epilogue
    #pragma unroll
    for (int mt2 = 0; mt2 < 2; mt2++) {
        const int r = mb*128 + (wid & 3)*32 + mt2*16 + grp;
        #pragma unroll
        for (int nt = 0; nt < 8; nt++) {
            const int c = nb*128 + (wid >> 2)*64 + nt*8 + 2*t4;
            const float bz0 = bias[c], bz1 = bias[c+1];
            *(float2*)&C[(size_t)r*N + c] =
                make_float2(acc[mt2][nt][0] + bz0, acc[mt2][nt][1] + bz1);
            *(float2*)&C[(size_t)(r+8)*N + c] =
                make_float2(acc[mt2][nt][2] + bz0, acc[mt2][nt][3] + bz1);
        }
    }
}

// ---------------- flash attention, tf32 mma.sync (unchanged from R3) ----------------
#define FB_R 128
#define FB_C 64
#define KS_ST 132   // HD + 4
#define VS_ST 136   // HD + 8
#define PS_ST 68    // BC + 4
#define FLASH_SMEM ((FB_C*KS_ST + FB_C*VS_ST + FB_R*PS_ST) * 4)

__global__ __launch_bounds__(256)
void flash_tf32(const float* __restrict__ Q, const float* __restrict__ Kg,
                const float* __restrict__ Vg, float* __restrict__ O)
{
    extern __shared__ float sm[];
    float* Ks = sm;                       // [64][KS_ST]
    float* Vs = Ks + FB_C*KS_ST;          // [64][VS_ST]
    float* Ps = Vs + FB_C*VS_ST;          // [8][16][PS_ST]

    const int tid  = threadIdx.x;
    const int lane = tid & 31;
    const int wid  = tid >> 5;
    const int grp  = lane >> 2;
    const int t4   = lane & 3;

    const int qb = gridDim.x - 1 - blockIdx.x;
    const int h  = blockIdx.y;
    const int b  = blockIdx.z;
    const int q0 = qb * FB_R;
    const int qr = q0 + wid*16 + grp;

    const float scale = 0.08838834764831845f;

    const float* Qb = Q + (size_t)b*TT*DD + (size_t)h*HD;
    uint32_t qf[16][4];
    #pragma unroll
    for (int ks = 0; ks < 16; ks++) {
        const float* p0 = &Qb[(size_t)qr*DD + ks*8 + t4];
        qf[ks][0] = __float_as_uint(f2tf(p0[0]        * scale));
        qf[ks][1] = __float_as_uint(f2tf(p0[8*DD]     * scale));
        qf[ks][2] = __float_as_uint(f2tf(p0[4]        * scale));
        qf[ks][3] = __float_as_uint(f2tf(p0[8*DD + 4] * scale));
    }

    float of[16][4];
    #pragma unroll
    for (int nt = 0; nt < 16; nt++)
        #pragma unroll
        for (int e = 0; e < 4; e++) of[nt][e] = 0.f;

    float m_lo = -1e30f, m_hi = -1e30f, l_lo = 0.f, l_hi = 0.f;

    const float* Kb = Kg + (size_t)b*TT*HD;
    const float* Vb = Vg + (size_t)b*TT*HD;
    float* Pw = Ps + wid*16*PS_ST;
    const int nkt = 2*(qb + 1);

    const int lr = tid >> 5;
    const int lc = (tid & 31) * 4;

    for (int kt = 0; kt < nkt; kt++) {
        const int k0 = kt * FB_C;
        __syncthreads();
        #pragma unroll
        for (int p = 0; p < 8; p++) {
            int rr = lr + p*8;
            float4 kv = *(const float4*)&Kb[(size_t)(k0 + rr)*HD + lc];
            float4 wk = make_float4(f2tf(kv.x), f2tf(kv.y), f2tf(kv.z), f2tf(kv.w));
            *(float4*)&Ks[rr*KS_ST + lc] = wk;
            float4 vv = *(const float4*)&Vb[(size_t)(k0 + rr)*HD + lc];
            float4 wv = make_float4(f2tf(vv.x), f2tf(vv.y), f2tf(vv.z), f2tf(vv.w));
            *(float4*)&Vs[rr*VS_ST + lc] = wv;
        }
        __syncthreads();

        float sacc[8][4];
        #pragma unroll
        for (int nt = 0; nt < 8; nt++)
            #pragma unroll
            for (int e = 0; e < 4; e++) sacc[nt][e] = 0.f;

        #pragma unroll
        for (int ks = 0; ks < 16; ks++) {
            #pragma unroll
            for (int nt = 0; nt < 8; nt++) {
                uint32_t bf[2];
                const float* kb = &Ks[(nt*8 + grp)*KS_ST + ks*8 + t4];
                bf[0] = __float_as_uint(kb[0]);
                bf[1] = __float_as_uint(kb[4]);
                mma_tf32(sacc[nt], qf[ks], bf);
            }
        }

        if (kt >= nkt - 2) {
            #pragma unroll
            for (int nt = 0; nt < 8; nt++) {
                int kc = k0 + nt*8 + 2*t4;
                if (kc     > qr)     sacc[nt][0] = -1e30f;
                if (kc + 1 > qr)     sacc[nt][1] = -1e30f;
                if (kc     > qr + 8) sacc[nt][2] = -1e30f;
                if (kc + 1 > qr + 8) sacc[nt][3] = -1e30f;
            }
        }

        float mx_lo = -1e30f, mx_hi = -1e30f;
        #pragma unroll
        for (int nt = 0; nt < 8; nt++) {
            mx_lo = fmaxf(mx_lo, fmaxf(sacc[nt][0], sacc[nt][1]));
            mx_hi = fmaxf(mx_hi, fmaxf(sacc[nt][2], sacc[nt][3]));
        }
        mx_lo = fmaxf(mx_lo, __shfl_xor_sync(0xffffffffu, mx_lo, 1));
        mx_lo = fmaxf(mx_lo, __shfl_xor_sync(0xffffffffu, mx_lo, 2));
        mx_hi = fmaxf(mx_hi, __shfl_xor_sync(0xffffffffu, mx_hi, 1));
        mx_hi = fmaxf(mx_hi, __shfl_xor_sync(0xffffffffu, mx_hi, 2));

        const float mn_lo = fmaxf(m_lo, mx_lo);
        const float mn_hi = fmaxf(m_hi, mx_hi);
        const float corr_lo = __expf(m_lo - mn_lo);
        const float corr_hi = __expf(m_hi - mn_hi);

        float sum_lo = 0.f, sum_hi = 0.f;
        #pragma unroll
        for (int nt = 0; nt < 8; nt++) {
            sacc[nt][0] = __expf(sacc[nt][0] - mn_lo);
            sacc[nt][1] = __expf(sacc[nt][1] - mn_lo);
            sacc[nt][2] = __expf(sacc[nt][2] - mn_hi);
            sacc[nt][3] = __expf(sacc[nt][3] - mn_hi);
            sum_lo += sacc[nt][0] + sacc[nt][1];
            sum_hi += sacc[nt][2] + sacc[nt][3];
        }
        sum_lo += __shfl_xor_sync(0xffffffffu, sum_lo, 1);
        sum_lo += __shfl_xor_sync(0xffffffffu, sum_lo, 2);
        sum_hi += __shfl_xor_sync(0xffffffffu, sum_hi, 1);
        sum_hi += __shfl_xor_sync(0xffffffffu, sum_hi, 2);

        l_lo = l_lo * corr_lo + sum_lo;  m_lo = mn_lo;
        l_hi = l_hi * corr_hi + sum_hi;  m_hi = mn_hi;

        #pragma unroll
        for (int nt = 0; nt < 16; nt++) {
            of[nt][0] *= corr_lo;  of[nt][1] *= corr_lo;
            of[nt][2] *= corr_hi;  of[nt][3] *= corr_hi;
        }

        #pragma unroll
        for (int nt = 0; nt < 8; nt++) {
            float2 p01 = make_float2(f2tf(sacc[nt][0]), f2tf(sacc[nt][1]));
            *(float2*)&Pw[grp*PS_ST + nt*8 + 2*t4] = p01;
            float2 p23 = make_float2(f2tf(sacc[nt][2]), f2tf(sacc[nt][3]));
            *(float2*)&Pw[(grp + 8)*PS_ST + nt*8 + 2*t4] = p23;
        }
        __syncwarp();

        #pragma unroll
        for (int ks = 0; ks < 8; ks++) {
            uint32_t pf[4];
            const float* pb = &Pw[grp*PS_ST + ks*8 + t4];
            pf[0] = __float_as_uint(pb[0]);
            pf[1] = __float_as_uint(pb[8*PS_ST]);
            pf[2] = __float_as_uint(pb[4]);
            pf[3] = __float_as_uint(pb[8*PS_ST + 4]);
            #pragma unroll
            for (int nt = 0; nt < 16; nt++) {
                uint32_t bf[2];
                const float* vb = &Vs[(ks*8 + t4)*VS_ST + nt*8 + grp];
                bf[0] = __float_as_uint(vb[0]);
                bf[1] = __float_as_uint(vb[4*VS_ST]);
                mma_tf32(of[nt], pf, bf);
            }
        }
    }

    // normalize, round to tf32 (feeds packed O-proj GEMM), write
    const float inv_lo = 1.f / l_lo;
    const float inv_hi = 1.f / l_hi;
    float* Ob = O + (size_t)b*TT*DD + (size_t)h*HD;
    #pragma unroll
    for (int nt = 0; nt < 16; nt++) {
        const int c = nt*8 + 2*t4;
        float2 v0 = make_float2(f2tf(of[nt][0]*inv_lo), f2tf(of[nt][1]*inv_lo));
        *(float2*)&Ob[(size_t)qr*DD + c] = v0;
        float2 v1 = make_float2(f2tf(of[nt][2]*inv_hi), f2tf(of[nt][3]*inv_hi));
        *(float2*)&Ob[(size_t)(qr + 8)*DD + c] = v1;
    }
}

// ---------------- launch ----------------
extern "C" void kernel_launch(void* const* d_in, const int* in_sizes, int n_in,
                              void* d_out, int out_size)
{
    const float* x  = (const float*)d_in[0];
    const float* Wq = (const float*)d_in[1];
    const float* bq = (const float*)d_in[2];
    const float* Wk = (const float*)d_in[3];
    const float* bk = (const float*)d_in[4];
    const float* Wv = (const float*)d_in[5];
    const float* bv = (const float*)d_in[6];
    const float* Wo = (const float*)d_in[7];
    const float* bo = (const float*)d_in[8];
    float* out = (float*)d_out;

    float *Qp, *Kp, *Vp, *AOr;
    float4 *Xp, *AOp, *WqP, *WkP, *WvP, *WoP;
    cudaGetSymbolAddress((void**)&Qp,  g_Q);
    cudaGetSymbolAddress((void**)&Kp,  g_K);
    cudaGetSymbolAddress((void**)&Vp,  g_V);
    cudaGetSymbolAddress((void**)&AOr, g_AO);
    cudaGetSymbolAddress((void**)&Xp,  g_Xp);
    cudaGetSymbolAddress((void**)&AOp, g_AOp);
    cudaGetSymbolAddress((void**)&WqP, g_WqP);
    cudaGetSymbolAddress((void**)&WkP, g_WkP);
    cudaGetSymbolAddress((void**)&WvP, g_WvP);
    cudaGetSymbolAddress((void**)&WoP, g_WoP);

    cudaFuncSetAttribute(gemm_mma,  cudaFuncAttributeMaxDynamicSharedMemorySize, G_SMEM);
    cudaFuncSetAttribute(flash_tf32, cudaFuncAttributeMaxDynamicSharedMemorySize, FLASH_SMEM);

    // ---- pack operands (tf32-rounded, fragment order) ----
    pack_A<<<MROWS*DD/4/256, 256>>>(x,  Xp,  MROWS, DD);
    pack_B<<<DD*DD/2/256,    256>>>(Wq, (float2*)WqP, DD, DD);
    pack_B<<<DD*HD/2/256,    256>>>(Wk, (float2*)WkP, HD, DD);
    pack_B<<<DD*HD/2/256,    256>>>(Wv, (float2*)WvP, HD, DD);
    pack_B<<<DD*DD/2/256,    256>>>(Wo, (float2*)WoP, DD, DD);

    // ---- projections ----
    gemm_mma<<<dim3(DD/128, MROWS/128), 256, G_SMEM>>>(Xp, WqP, bq, Qp, MROWS, DD, DD);
    gemm_mma<<<dim3(1,      MROWS/128), 256, G_SMEM>>>(Xp, WkP, bk, Kp, MROWS, HD, DD);
    gemm_mma<<<dim3(1,      MROWS/128), 256, G_SMEM>>>(Xp, WvP, bv, Vp, MROWS, HD, DD);

    // ---- attention ----
    flash_tf32<<<dim3(TT/FB_R, HH, BB), 256, FLASH_SMEM>>>(Qp, Kp, Vp, AOr);

    // ---- output projection ----
    pack_A<<<MROWS*DD/4/256, 256>>>(AOr, AOp, MROWS, DD);
    gemm_mma<<<dim3(DD/128, MROWS/128), 256, G_SMEM>>>(AOp, WoP, bo, out, MROWS, DD, DD);
}